// round 1
// baseline (speedup 1.0000x reference)
#include <cuda_runtime.h>

#define NB 16
#define NC 64
#define HW 65536
#define NBINS 256

// ---- scratch (no allocations allowed) ----
__device__ float         d_mean[NB * NC];
__device__ float         d_ascaled[NB * NC];
__device__ unsigned int  d_hist[NB * NBINS];
__device__ float         d_scale[NB * NBINS];
__device__ unsigned char d_q[NB * HW];

// ============================================================
// Pass 1: per-(b,c) plane mean.  grid = NB*NC blocks, 256 thr
// ============================================================
__global__ void k_mean(const float* __restrict__ F) {
    const int plane = blockIdx.x;                 // b*NC + c
    const int tid = threadIdx.x;
    const float4* p = (const float4*)(F + (size_t)plane * HW);
    float s = 0.f;
    #pragma unroll 8
    for (int j = 0; j < HW / 4 / 256; ++j) {      // 64 float4 per thread
        float4 v = p[j * 256 + tid];
        s += (v.x + v.y) + (v.z + v.w);
    }
    __shared__ float red[256];
    red[tid] = s;
    __syncthreads();
    for (int o = 128; o > 0; o >>= 1) {
        if (tid < o) red[tid] += red[tid + o];
        __syncthreads();
    }
    if (tid == 0) d_mean[plane] = red[0] * (1.0f / HW);
}

// ============================================================
// Pass 2: a_scaled = a / max(||a||, eps), zero histograms.
// grid = NB blocks, 256 thr
// ============================================================
__global__ void k_prep() {
    const int b = blockIdx.x, tid = threadIdx.x;
    __shared__ float a[NC];
    __shared__ float inv_na;
    if (tid < NC) a[tid] = d_mean[b * NC + tid];
    d_hist[b * NBINS + tid] = 0u;
    __syncthreads();
    if (tid == 0) {
        float ss = 0.f;
        for (int c = 0; c < NC; ++c) ss += a[c] * a[c];
        inv_na = 1.0f / fmaxf(sqrtf(ss), 1e-12f);
    }
    __syncthreads();
    if (tid < NC) d_ascaled[b * NC + tid] = a[tid] * inv_na;
}

// ============================================================
// Pass 3: cosine map, quantize, histogram, store q.
// grid = NB * 64 blocks, 256 thr (each thread = 4 pixels)
// ============================================================
__device__ __forceinline__ int quant(float d, float ss) {
    float c = d / fmaxf(sqrtf(ss), 1e-12f);
    return ((int)(c * 255.0f)) & 255;   // trunc-toward-zero, then floor-mod 256
}

__global__ void k_cos(const float* __restrict__ F) {
    const int b   = blockIdx.x >> 6;
    const int blk = blockIdx.x & 63;
    const int tid = threadIdx.x;
    const int p4  = blk * 256 + tid;              // float4 pixel index in batch

    __shared__ float as[NC];
    __shared__ unsigned int sh[NBINS];
    if (tid < NC) as[tid] = d_ascaled[b * NC + tid];
    sh[tid] = 0u;
    __syncthreads();

    const float4* p = (const float4*)(F + (size_t)b * NC * HW) + p4;
    float d0 = 0.f, d1 = 0.f, d2 = 0.f, d3 = 0.f;
    float s0 = 0.f, s1 = 0.f, s2 = 0.f, s3 = 0.f;
    #pragma unroll 8
    for (int c = 0; c < NC; ++c) {
        float4 v = p[c * (HW / 4)];
        float ac = as[c];
        d0 += ac * v.x; d1 += ac * v.y; d2 += ac * v.z; d3 += ac * v.w;
        s0 += v.x * v.x; s1 += v.y * v.y; s2 += v.z * v.z; s3 += v.w * v.w;
    }

    int q0 = quant(d0, s0), q1 = quant(d1, s1);
    int q2 = quant(d2, s2), q3 = quant(d3, s3);

    atomicAdd(&sh[q0], 1u); atomicAdd(&sh[q1], 1u);
    atomicAdd(&sh[q2], 1u); atomicAdd(&sh[q3], 1u);

    uchar4 qv = make_uchar4((unsigned char)q0, (unsigned char)q1,
                            (unsigned char)q2, (unsigned char)q3);
    *(uchar4*)(d_q + ((size_t)b << 16) + ((size_t)p4 << 2)) = qv;

    __syncthreads();
    unsigned int cnt = sh[tid];
    if (cnt) atomicAdd(&d_hist[b * NBINS + tid], cnt);
}

// ============================================================
// Pass 4: per-batch LUT.  grid = NB blocks, 256 thr
// ============================================================
__global__ void k_lut() {
    const int b = blockIdx.x, tid = threadIdx.x;
    __shared__ float cdf[NBINS];
    __shared__ float tmp[NBINS];

    float h = (float)d_hist[b * NBINS + tid];
    cdf[tid] = h;
    __syncthreads();
    // inclusive scan (Hillis-Steele)
    for (int o = 1; o < NBINS; o <<= 1) {
        float v = cdf[tid];
        float add = (tid >= o) ? cdf[tid - o] : 0.f;
        __syncthreads();
        cdf[tid] = v + add;
        __syncthreads();
    }
    // cdf at first non-empty bin == min over bins with hist>0
    tmp[tid] = (h > 0.f) ? cdf[tid] : (float)(HW + 1);
    __syncthreads();
    for (int o = 128; o > 0; o >>= 1) {
        if (tid < o) tmp[tid] = fminf(tmp[tid], tmp[tid + o]);
        __syncthreads();
    }
    float cmin  = tmp[0];
    float denom = fmaxf((float)HW - cmin, 1.0f);
    float r     = 255.0f / denom;
    float lut   = rintf((cdf[tid] - cmin) * r);     // round-half-even == jnp.round
    lut = fminf(fmaxf(lut, 0.0f), 255.0f);
    d_scale[b * NBINS + tid] = lut / 255.0f;
}

// ============================================================
// Pass 5: out = F * scale[b][q[b,pixel]].
// grid = (NB*NC*HW/4)/256 = 65536 blocks, 256 thr
// ============================================================
__global__ void k_mul(const float* __restrict__ F, float* __restrict__ out) {
    const int tid = threadIdx.x;
    const int i = blockIdx.x * 256 + tid;         // float4 element index
    const int b = i >> 20;                        // NC*HW/4 = 2^20 float4 per batch
    const int p4 = i & 16383;                     // HW/4 = 16384 float4 per plane

    __shared__ float sc[NBINS];
    sc[tid] = d_scale[b * NBINS + tid];           // b uniform per block (4096 blk/batch)
    __syncthreads();

    uchar4 q = *(const uchar4*)(d_q + ((size_t)b << 16) + ((size_t)p4 << 2));
    float4 v = ((const float4*)F)[i];
    float4 o;
    o.x = v.x * sc[q.x];
    o.y = v.y * sc[q.y];
    o.z = v.z * sc[q.z];
    o.w = v.w * sc[q.w];
    ((float4*)out)[i] = o;
}

// ============================================================
extern "C" void kernel_launch(void* const* d_in, const int* in_sizes, int n_in,
                              void* d_out, int out_size) {
    const float* F = (const float*)d_in[0];
    float* out = (float*)d_out;
    (void)in_sizes; (void)n_in; (void)out_size;

    k_mean<<<NB * NC, 256>>>(F);
    k_prep<<<NB, 256>>>();
    k_cos<<<NB * 64, 256>>>(F);
    k_lut<<<NB, 256>>>();
    k_mul<<<(NB * NC * HW / 4) / 256, 256>>>(F, out);
}